// round 1
// baseline (speedup 1.0000x reference)
#include <cuda_runtime.h>
#include <math.h>

// Problem dims
#define HD    512          // H
#define EMBD  256          // E
#define VOCAB 50000        // V
#define BATCH 128          // B
#define SEQ   200          // S
#define G3H   (3*HD)       // 1536
#define KGRU  (2*HD+EMBD)  // 1280
#define KOUT  (3*HD+EMBD)  // 1792

// Scratch (device globals — no allocation allowed)
__device__ float g_weff[2*HD];            // 1024: enc-part of attn_w^T v
__device__ float g_scores[BATCH*SEQ];
__device__ float g_togru[BATCH*KGRU];     // [emb(256) | relu(context)(1024)] -- whole thing relu'd
__device__ float g_toout[BATCH*KOUT];     // [h_new(512) | context(1024) | emb(256)]
__device__ float g_gi[BATCH*G3H];
__device__ float g_gh[BATCH*G3H];

// ---------------------------------------------------------------------------
// K0: w_eff[k] = sum_h v[h] * attn_w[h, 512+k], k in [0,1024)
// (h0 part and attn_b cancel under softmax -> not needed)
// ---------------------------------------------------------------------------
__global__ void k_weff(const float* __restrict__ attn_w, const float* __restrict__ v) {
    int k = blockIdx.x * blockDim.x + threadIdx.x;   // grid 4 x 256 -> 1024
    float s = 0.f;
    #pragma unroll 4
    for (int h = 0; h < HD; ++h)
        s += v[h] * attn_w[(size_t)h * G3H + HD + k];
    g_weff[k] = s;
}

// ---------------------------------------------------------------------------
// K1: scores[b,s] = dot(enc_out[b,s,:], w_eff)   (one warp per (b,s))
// ---------------------------------------------------------------------------
__global__ __launch_bounds__(256) void k_scores(const float* __restrict__ enc) {
    __shared__ float sw[2*HD];
    int tid = threadIdx.x;
    for (int i = tid; i < 2*HD; i += 256) sw[i] = g_weff[i];
    __syncthreads();
    int warp = tid >> 5, lane = tid & 31;
    int idx = blockIdx.x * 8 + warp;                 // 3200 blocks * 8 warps = 25600
    const float* p = enc + (size_t)idx * (2*HD);
    float s = 0.f;
    #pragma unroll
    for (int i = 0; i < 32; ++i)
        s += p[lane + 32*i] * sw[lane + 32*i];
    #pragma unroll
    for (int o = 16; o; o >>= 1) s += __shfl_xor_sync(0xffffffffu, s, o);
    if (lane == 0) g_scores[idx] = s;
}

// ---------------------------------------------------------------------------
// K2: per-batch softmax + context + build to_gru / to_out (context & emb parts)
// ---------------------------------------------------------------------------
__global__ __launch_bounds__(256) void k_ctx(const float* __restrict__ enc,
                                             const float* __restrict__ emb,
                                             const int* __restrict__ x) {
    __shared__ float attn[SEQ];
    __shared__ float red[256];
    int b = blockIdx.x, tid = threadIdx.x;
    float sc = (tid < SEQ) ? g_scores[b*SEQ + tid] : -1e30f;
    red[tid] = sc; __syncthreads();
    #pragma unroll
    for (int o = 128; o; o >>= 1) { if (tid < o) red[tid] = fmaxf(red[tid], red[tid+o]); __syncthreads(); }
    float mx = red[0]; __syncthreads();
    float e = (tid < SEQ) ? expf(sc - mx) : 0.f;
    red[tid] = e; __syncthreads();
    #pragma unroll
    for (int o = 128; o; o >>= 1) { if (tid < o) red[tid] += red[tid+o]; __syncthreads(); }
    float inv = 1.f / red[0];
    if (tid < SEQ) attn[tid] = e * inv;
    __syncthreads();

    float a0=0.f, a1=0.f, a2=0.f, a3=0.f;
    const float* pb = enc + (size_t)b * SEQ * (2*HD);
    #pragma unroll 4
    for (int s = 0; s < SEQ; ++s) {
        float a = attn[s];
        const float* p = pb + s * (2*HD);
        a0 += a * p[tid      ];
        a1 += a * p[tid + 256];
        a2 += a * p[tid + 512];
        a3 += a * p[tid + 768];
    }
    float vals[4] = {a0, a1, a2, a3};
    #pragma unroll
    for (int j = 0; j < 4; ++j) {
        int d = tid + 256*j;
        g_toout[(size_t)b*KOUT + HD + d]   = vals[j];            // to_out context
        g_togru[(size_t)b*KGRU + EMBD + d] = fmaxf(vals[j], 0.f); // relu(context)
    }
    // embedding gather (all 256 threads, E=256)
    float ev = emb[(size_t)x[b] * EMBD + tid];
    g_togru[(size_t)b*KGRU + tid]            = fmaxf(ev, 0.f);
    g_toout[(size_t)b*KOUT + 3*HD + tid]     = ev;
}

// ---------------------------------------------------------------------------
// Generic SGEMM: C[m,n] = sum_k A[m,k]*B[n,k] + bias[n]
// M fixed = 128 (BM=128), BN=64, BK=16, 256 threads, 8x4 per thread.
// ---------------------------------------------------------------------------
__global__ __launch_bounds__(256, 2) void sgemm128(
    const float* __restrict__ A, const float* __restrict__ Bm,
    const float* __restrict__ bias, float* __restrict__ C,
    int N, int K, int ldc)
{
    __shared__ float As[16][128];   // [k][m]
    __shared__ float Bs[16][64];    // [k][n]
    int tid = threadIdx.x;
    int n0  = blockIdx.x * 64;
    int tx  = tid & 15;             // n-group 0..15 (4 n each)
    int ty  = tid >> 4;             // m-group 0..15 (8 m each)

    float acc[8][4];
    #pragma unroll
    for (int i = 0; i < 8; ++i)
        #pragma unroll
        for (int j = 0; j < 4; ++j) acc[i][j] = 0.f;

    for (int k0 = 0; k0 < K; k0 += 16) {
        // load A tile: 512 float4, 2 per thread, scatter-transpose into As[k][m]
        #pragma unroll
        for (int r = 0; r < 2; ++r) {
            int l = tid + 256*r;
            int m = l >> 2, kq = l & 3;
            float4 f = *(const float4*)(A + (size_t)m * K + k0 + kq*4);
            As[kq*4+0][m] = f.x; As[kq*4+1][m] = f.y;
            As[kq*4+2][m] = f.z; As[kq*4+3][m] = f.w;
        }
        // load B tile: 256 float4, 1 per thread, scatter-transpose into Bs[k][n]
        {
            int n = tid >> 2, kq = tid & 3;
            float4 f = make_float4(0.f, 0.f, 0.f, 0.f);
            if (n0 + n < N)
                f = *(const float4*)(Bm + (size_t)(n0+n) * K + k0 + kq*4);
            Bs[kq*4+0][n] = f.x; Bs[kq*4+1][n] = f.y;
            Bs[kq*4+2][n] = f.z; Bs[kq*4+3][n] = f.w;
        }
        __syncthreads();
        #pragma unroll
        for (int kk = 0; kk < 16; ++kk) {
            float4 b4  = *(const float4*)&Bs[kk][tx*4];
            float4 a4a = *(const float4*)&As[kk][ty*8];
            float4 a4b = *(const float4*)&As[kk][ty*8+4];
            float af[8] = {a4a.x,a4a.y,a4a.z,a4a.w, a4b.x,a4b.y,a4b.z,a4b.w};
            float bf[4] = {b4.x,b4.y,b4.z,b4.w};
            #pragma unroll
            for (int i = 0; i < 8; ++i)
                #pragma unroll
                for (int j = 0; j < 4; ++j)
                    acc[i][j] = fmaf(af[i], bf[j], acc[i][j]);
        }
        __syncthreads();
    }

    int n = n0 + tx*4;
    if (n < N) {
        float bb[4];
        #pragma unroll
        for (int j = 0; j < 4; ++j) bb[j] = bias ? bias[n+j] : 0.f;
        #pragma unroll
        for (int i = 0; i < 8; ++i) {
            int m = ty*8 + i;
            float4 o = make_float4(acc[i][0]+bb[0], acc[i][1]+bb[1],
                                   acc[i][2]+bb[2], acc[i][3]+bb[3]);
            *(float4*)(C + (size_t)m * ldc + n) = o;
        }
    }
}

// ---------------------------------------------------------------------------
// K4: GRU gate combine -> h_new into to_out[:,0:512] and d_out tail
// ---------------------------------------------------------------------------
__global__ void k_gru(const float* __restrict__ hidden, float* __restrict__ out_h, int write_h) {
    int idx = blockIdx.x * blockDim.x + threadIdx.x;   // 65536
    int b = idx >> 9, i = idx & 511;
    size_t base = (size_t)b * G3H;
    float ir = g_gi[base + i],        hr = g_gh[base + i];
    float iz = g_gi[base + HD + i],   hz = g_gh[base + HD + i];
    float in_ = g_gi[base + 2*HD + i], hn = g_gh[base + 2*HD + i];
    float r = 1.f / (1.f + expf(-(ir + hr)));
    float z = 1.f / (1.f + expf(-(iz + hz)));
    float n = tanhf(in_ + r * hn);
    float h = hidden[idx];
    float hnew = (1.f - z) * n + z * h;
    g_toout[(size_t)b * KOUT + i] = hnew;
    if (write_h) out_h[idx] = hnew;
}

// ---------------------------------------------------------------------------
extern "C" void kernel_launch(void* const* d_in, const int* in_sizes, int n_in,
                              void* d_out, int out_size) {
    const int*   x      = (const int*)  d_in[0];
    const float* hidden = (const float*)d_in[1];
    const float* enc    = (const float*)d_in[2];
    const float* emb    = (const float*)d_in[3];
    const float* attn_w = (const float*)d_in[4];
    // d_in[5] = attn_b : cancels under softmax (constant shift per (b,s))
    const float* v      = (const float*)d_in[6];
    const float* w_ih   = (const float*)d_in[7];
    const float* w_hh   = (const float*)d_in[8];
    const float* b_ih   = (const float*)d_in[9];
    const float* b_hh   = (const float*)d_in[10];
    const float* out_w  = (const float*)d_in[11];
    const float* out_b  = (const float*)d_in[12];
    float* out = (float*)d_out;

    // scratch symbol addresses (query only — no allocation)
    float *p_togru, *p_toout, *p_gi, *p_gh;
    cudaGetSymbolAddress((void**)&p_togru, g_togru);
    cudaGetSymbolAddress((void**)&p_toout, g_toout);
    cudaGetSymbolAddress((void**)&p_gi,    g_gi);
    cudaGetSymbolAddress((void**)&p_gh,    g_gh);

    k_weff  <<<4,    256>>>(attn_w, v);
    k_scores<<<3200, 256>>>(enc);
    k_ctx   <<<BATCH,256>>>(enc, emb, x);

    // GRU gate GEMMs: gi = to_gru @ w_ih^T + b_ih ; gh = h0 @ w_hh^T + b_hh
    sgemm128<<<G3H/64, 256>>>(p_togru, w_ih, b_ih, p_gi, G3H, KGRU, G3H);
    sgemm128<<<G3H/64, 256>>>(hidden,  w_hh, b_hh, p_gh, G3H, HD,   G3H);

    int write_h = (out_size >= BATCH*VOCAB + BATCH*HD) ? 1 : 0;
    k_gru<<<(BATCH*HD)/256, 256>>>(hidden, out + (size_t)BATCH*VOCAB, write_h);

    // logits = to_out @ out_w^T + out_b  -> d_out[0 : B*V)
    sgemm128<<<(VOCAB + 63)/64, 256>>>(p_toout, out_w, out_b, out, VOCAB, KOUT, VOCAB);
}

// round 3
// speedup vs baseline: 2.3773x; 2.3773x over previous
#include <cuda_runtime.h>
#include <math.h>
#include <stdint.h>

#define HD    512
#define EMBD  256
#define VOCAB 50000
#define BATCH 128
#define SEQ   200
#define G3H   (3*HD)       // 1536
#define KGRU  (2*HD+EMBD)  // 1280
#define KOUT  (3*HD+EMBD)  // 1792

// Scratch (device globals — no allocation allowed)
__device__ float g_weff[2*HD];
__device__ float g_scores[BATCH*SEQ];
__device__ float g_attn[BATCH*SEQ];
__device__ float g_ctx[BATCH*2*HD];
__device__ float g_togru[BATCH*KGRU];
__device__ float g_toout[BATCH*KOUT];
__device__ float g_gi[BATCH*G3H];
__device__ float g_gh[BATCH*G3H];

// ---------------------------------------------------------------------------
// helpers
// ---------------------------------------------------------------------------
__device__ __forceinline__ uint32_t f2tf32(float x) {
    uint32_t r;
    asm("cvt.rna.tf32.f32 %0, %1;" : "=r"(r) : "f"(x));
    return r;
}

__device__ __forceinline__ void mma_tf32(float* c, const uint32_t* a, const uint32_t* b) {
    asm volatile(
        "mma.sync.aligned.m16n8k8.row.col.f32.tf32.tf32.f32 "
        "{%0,%1,%2,%3}, {%4,%5,%6,%7}, {%8,%9}, {%0,%1,%2,%3};"
        : "+f"(c[0]), "+f"(c[1]), "+f"(c[2]), "+f"(c[3])
        : "r"(a[0]), "r"(a[1]), "r"(a[2]), "r"(a[3]), "r"(b[0]), "r"(b[1]));
}

// ---------------------------------------------------------------------------
// K0: w_eff[k] = sum_h v[h]*attn_w[h,512+k]  (h0 part + attn_b cancel in softmax)
// grid (8 k-chunks, 8 h-chunks) x 128 thr, atomicAdd into zeroed g_weff
// ---------------------------------------------------------------------------
__global__ void k_weff(const float* __restrict__ attn_w, const float* __restrict__ v) {
    int k  = blockIdx.x * 128 + threadIdx.x;
    int h0 = blockIdx.y * 64;
    float s = 0.f;
    #pragma unroll 8
    for (int h = h0; h < h0 + 64; ++h)
        s += v[h] * attn_w[(size_t)h * G3H + HD + k];
    atomicAdd(&g_weff[k], s);
}

// ---------------------------------------------------------------------------
// K1: scores[b,s] = dot(enc_out[b,s,:], w_eff)  (one warp per (b,s))
// ---------------------------------------------------------------------------
__global__ __launch_bounds__(256) void k_scores(const float* __restrict__ enc) {
    __shared__ float sw[2*HD];
    int tid = threadIdx.x;
    for (int i = tid; i < 2*HD; i += 256) sw[i] = g_weff[i];
    __syncthreads();
    int warp = tid >> 5, lane = tid & 31;
    int idx = blockIdx.x * 8 + warp;                 // 3200*8 = 25600 = B*S
    const float* p = enc + (size_t)idx * (2*HD);
    float s = 0.f;
    #pragma unroll
    for (int i = 0; i < 32; ++i)
        s += p[lane + 32*i] * sw[lane + 32*i];
    #pragma unroll
    for (int o = 16; o; o >>= 1) s += __shfl_xor_sync(0xffffffffu, s, o);
    if (lane == 0) g_scores[idx] = s;
}

// ---------------------------------------------------------------------------
// K2: softmax over S=200 per batch
// ---------------------------------------------------------------------------
__global__ __launch_bounds__(256) void k_softmax() {
    __shared__ float red[256];
    int b = blockIdx.x, tid = threadIdx.x;
    float sc = (tid < SEQ) ? g_scores[b*SEQ + tid] : -1e30f;
    red[tid] = sc; __syncthreads();
    #pragma unroll
    for (int o = 128; o; o >>= 1) { if (tid < o) red[tid] = fmaxf(red[tid], red[tid+o]); __syncthreads(); }
    float mx = red[0]; __syncthreads();
    float e = (tid < SEQ) ? expf(sc - mx) : 0.f;
    red[tid] = e; __syncthreads();
    #pragma unroll
    for (int o = 128; o; o >>= 1) { if (tid < o) red[tid] += red[tid+o]; __syncthreads(); }
    if (tid < SEQ) g_attn[b*SEQ + tid] = e / red[0];
}

// ---------------------------------------------------------------------------
// K3: context accumulation, split over 4 S-chunks, atomicAdd into g_ctx
// ---------------------------------------------------------------------------
__global__ __launch_bounds__(256) void k_ctx(const float* __restrict__ enc) {
    __shared__ float attn[64];
    int b = blockIdx.x, c = blockIdx.y, tid = threadIdx.x;
    if (tid < 50) attn[tid] = g_attn[b*SEQ + c*50 + tid];
    __syncthreads();
    const float* pb = enc + (size_t)b * SEQ * (2*HD) + (size_t)c * 50 * (2*HD);
    float a0 = 0.f, a1 = 0.f, a2 = 0.f, a3 = 0.f;
    #pragma unroll 2
    for (int s = 0; s < 50; ++s) {
        float a = attn[s];
        const float* p = pb + s * (2*HD);
        a0 += a * p[tid      ];
        a1 += a * p[tid + 256];
        a2 += a * p[tid + 512];
        a3 += a * p[tid + 768];
    }
    atomicAdd(&g_ctx[b*(2*HD) + tid      ], a0);
    atomicAdd(&g_ctx[b*(2*HD) + tid + 256], a1);
    atomicAdd(&g_ctx[b*(2*HD) + tid + 512], a2);
    atomicAdd(&g_ctx[b*(2*HD) + tid + 768], a3);
}

// ---------------------------------------------------------------------------
// K4: pack to_gru / to_out (context + embedding parts)
// ---------------------------------------------------------------------------
__global__ void k_pack(const float* __restrict__ emb, const int* __restrict__ x) {
    int b = blockIdx.x, tid = threadIdx.x;
    #pragma unroll
    for (int j = 0; j < 4; ++j) {
        int d = tid + 256*j;
        float cv = g_ctx[b*(2*HD) + d];
        g_toout[(size_t)b*KOUT + HD + d]   = cv;
        g_togru[(size_t)b*KGRU + EMBD + d] = fmaxf(cv, 0.f);
    }
    float ev = emb[(size_t)x[b] * EMBD + tid];
    g_togru[(size_t)b*KGRU + tid]        = fmaxf(ev, 0.f);
    g_toout[(size_t)b*KOUT + 3*HD + tid] = ev;
}

// ---------------------------------------------------------------------------
// Split-K SGEMM (fp32): C[m,n] += sum_{k in slice} A[m,k]*B[n,k] via atomicAdd
// BM=128, BN=64, BK=16, 256 thr, 8x4 per thread. grid (N/64, n_slices)
// ---------------------------------------------------------------------------
__global__ __launch_bounds__(256, 2) void sgemm_sk(
    const float* __restrict__ A, const float* __restrict__ Bm,
    float* __restrict__ C, int N, int K, int ldc, int kslice)
{
    __shared__ float As[16][128];
    __shared__ float Bs[16][64];
    int tid = threadIdx.x;
    int n0  = blockIdx.x * 64;
    int kb  = blockIdx.y * kslice;
    int ke  = kb + kslice; if (ke > K) ke = K;
    int tx  = tid & 15;
    int ty  = tid >> 4;

    float acc[8][4];
    #pragma unroll
    for (int i = 0; i < 8; ++i)
        #pragma unroll
        for (int j = 0; j < 4; ++j) acc[i][j] = 0.f;

    for (int k0 = kb; k0 < ke; k0 += 16) {
        #pragma unroll
        for (int r = 0; r < 2; ++r) {
            int l = tid + 256*r;
            int m = l >> 2, kq = l & 3;
            float4 f = *(const float4*)(A + (size_t)m * K + k0 + kq*4);
            As[kq*4+0][m] = f.x; As[kq*4+1][m] = f.y;
            As[kq*4+2][m] = f.z; As[kq*4+3][m] = f.w;
        }
        {
            int n = tid >> 2, kq = tid & 3;
            float4 f = make_float4(0.f, 0.f, 0.f, 0.f);
            if (n0 + n < N)
                f = *(const float4*)(Bm + (size_t)(n0+n) * K + k0 + kq*4);
            Bs[kq*4+0][n] = f.x; Bs[kq*4+1][n] = f.y;
            Bs[kq*4+2][n] = f.z; Bs[kq*4+3][n] = f.w;
        }
        __syncthreads();
        #pragma unroll
        for (int kk = 0; kk < 16; ++kk) {
            float4 b4  = *(const float4*)&Bs[kk][tx*4];
            float4 a4a = *(const float4*)&As[kk][ty*8];
            float4 a4b = *(const float4*)&As[kk][ty*8+4];
            float af[8] = {a4a.x,a4a.y,a4a.z,a4a.w, a4b.x,a4b.y,a4b.z,a4b.w};
            float bf[4] = {b4.x,b4.y,b4.z,b4.w};
            #pragma unroll
            for (int i = 0; i < 8; ++i)
                #pragma unroll
                for (int j = 0; j < 4; ++j)
                    acc[i][j] = fmaf(af[i], bf[j], acc[i][j]);
        }
        __syncthreads();
    }

    int n = n0 + tx*4;
    if (n < N) {
        #pragma unroll
        for (int i = 0; i < 8; ++i) {
            int m = ty*8 + i;
            #pragma unroll
            for (int j = 0; j < 4; ++j)
                atomicAdd(&C[(size_t)m * ldc + n + j], acc[i][j]);
        }
    }
}

// ---------------------------------------------------------------------------
// K5: GRU gate combine (biases added here) -> h_new into to_out + d_out tail
// ---------------------------------------------------------------------------
__global__ void k_gru(const float* __restrict__ hidden,
                      const float* __restrict__ b_ih, const float* __restrict__ b_hh,
                      float* __restrict__ out_h, int write_h) {
    int idx = blockIdx.x * blockDim.x + threadIdx.x;   // 65536
    int b = idx >> 9, i = idx & 511;
    size_t base = (size_t)b * G3H;
    float ir = g_gi[base + i]        + b_ih[i];
    float hr = g_gh[base + i]        + b_hh[i];
    float iz = g_gi[base + HD + i]   + b_ih[HD + i];
    float hz = g_gh[base + HD + i]   + b_hh[HD + i];
    float in_= g_gi[base + 2*HD + i] + b_ih[2*HD + i];
    float hn = g_gh[base + 2*HD + i] + b_hh[2*HD + i];
    float r = 1.f / (1.f + expf(-(ir + hr)));
    float z = 1.f / (1.f + expf(-(iz + hz)));
    float n = tanhf(in_ + r * hn);
    float h = hidden[idx];
    float hnew = (1.f - z) * n + z * h;
    g_toout[(size_t)b * KOUT + i] = hnew;
    if (write_h) out_h[idx] = hnew;
}

// ---------------------------------------------------------------------------
// K6: logits GEMM via TF32 tensor-core mma: C[128,V] = A[128,K] @ B[V,K]^T + bias
// BM=128, BN=128, BK=16; 8 warps (4M x 2N), warp tile 32x64
// ---------------------------------------------------------------------------
__global__ __launch_bounds__(256, 2) void k_logits(
    const float* __restrict__ A, const float* __restrict__ Bw,
    const float* __restrict__ bias, float* __restrict__ C)
{
    __shared__ uint32_t As[128][20];   // [m][k], pad 20 -> conflict-free frag loads
    __shared__ uint32_t Bs[128][20];   // [n][k]
    int tid  = threadIdx.x;
    int wid  = tid >> 5, lane = tid & 31;
    int gid  = lane >> 2, tig = lane & 3;
    int n0   = blockIdx.x * 128;
    int wm   = (wid & 3) * 32;         // warp M offset
    int wn   = (wid >> 2) * 64;        // warp N offset
    int lm   = tid >> 2;               // 0..63 load row
    int lk   = (tid & 3) * 4;          // 0,4,8,12 load k offset

    float acc[2][8][4];
    #pragma unroll
    for (int mt = 0; mt < 2; ++mt)
        #pragma unroll
        for (int nt = 0; nt < 8; ++nt)
            #pragma unroll
            for (int j = 0; j < 4; ++j) acc[mt][nt][j] = 0.f;

    for (int k0 = 0; k0 < KOUT; k0 += 16) {
        // A tile -> smem (tf32)
        #pragma unroll
        for (int h = 0; h < 2; ++h) {
            int m = lm + h*64;
            float4 f = *(const float4*)(A + (size_t)m * KOUT + k0 + lk);
            As[m][lk+0] = f2tf32(f.x); As[m][lk+1] = f2tf32(f.y);
            As[m][lk+2] = f2tf32(f.z); As[m][lk+3] = f2tf32(f.w);
        }
        // B tile -> smem (tf32), guard tail rows
        #pragma unroll
        for (int h = 0; h < 2; ++h) {
            int n = lm + h*64;
            int gn = n0 + n;
            float4 f = make_float4(0.f, 0.f, 0.f, 0.f);
            if (gn < VOCAB)
                f = *(const float4*)(Bw + (size_t)gn * KOUT + k0 + lk);
            Bs[n][lk+0] = f2tf32(f.x); Bs[n][lk+1] = f2tf32(f.y);
            Bs[n][lk+2] = f2tf32(f.z); Bs[n][lk+3] = f2tf32(f.w);
        }
        __syncthreads();
        #pragma unroll
        for (int ks = 0; ks < 2; ++ks) {
            int kb = ks * 8;
            uint32_t af[2][4];
            #pragma unroll
            for (int mt = 0; mt < 2; ++mt) {
                int r = wm + mt*16;
                af[mt][0] = As[r + gid    ][kb + tig];
                af[mt][1] = As[r + gid + 8][kb + tig];
                af[mt][2] = As[r + gid    ][kb + tig + 4];
                af[mt][3] = As[r + gid + 8][kb + tig + 4];
            }
            #pragma unroll
            for (int nt = 0; nt < 8; ++nt) {
                uint32_t bf[2];
                int nn = wn + nt*8 + gid;
                bf[0] = Bs[nn][kb + tig];
                bf[1] = Bs[nn][kb + tig + 4];
                mma_tf32(acc[0][nt], af[0], bf);
                mma_tf32(acc[1][nt], af[1], bf);
            }
        }
        __syncthreads();
    }

    #pragma unroll
    for (int mt = 0; mt < 2; ++mt) {
        #pragma unroll
        for (int nt = 0; nt < 8; ++nt) {
            int n = n0 + wn + nt*8 + 2*tig;
            if (n < VOCAB) {   // n even, VOCAB even -> n+1 < VOCAB too
                int m = wm + mt*16 + gid;
                float b0 = bias[n], b1 = bias[n+1];
                float2 v0 = make_float2(acc[mt][nt][0] + b0, acc[mt][nt][1] + b1);
                float2 v1 = make_float2(acc[mt][nt][2] + b0, acc[mt][nt][3] + b1);
                *(float2*)(C + (size_t)m     * VOCAB + n) = v0;
                *(float2*)(C + (size_t)(m+8) * VOCAB + n) = v1;
            }
        }
    }
}

// ---------------------------------------------------------------------------
extern "C" void kernel_launch(void* const* d_in, const int* in_sizes, int n_in,
                              void* d_out, int out_size) {
    const int*   x      = (const int*)  d_in[0];
    const float* hidden = (const float*)d_in[1];
    const float* enc    = (const float*)d_in[2];
    const float* emb    = (const float*)d_in[3];
    const float* attn_w = (const float*)d_in[4];
    // d_in[5] = attn_b : cancels under softmax
    const float* v      = (const float*)d_in[6];
    const float* w_ih   = (const float*)d_in[7];
    const float* w_hh   = (const float*)d_in[8];
    const float* b_ih   = (const float*)d_in[9];
    const float* b_hh   = (const float*)d_in[10];
    const float* out_w  = (const float*)d_in[11];
    const float* out_b  = (const float*)d_in[12];
    float* out = (float*)d_out;

    float *p_weff, *p_ctx, *p_togru, *p_toout, *p_gi, *p_gh;
    cudaGetSymbolAddress((void**)&p_weff,  g_weff);
    cudaGetSymbolAddress((void**)&p_ctx,   g_ctx);
    cudaGetSymbolAddress((void**)&p_togru, g_togru);
    cudaGetSymbolAddress((void**)&p_toout, g_toout);
    cudaGetSymbolAddress((void**)&p_gi,    g_gi);
    cudaGetSymbolAddress((void**)&p_gh,    g_gh);

    cudaMemsetAsync(p_weff, 0, sizeof(float)*2*HD);
    cudaMemsetAsync(p_ctx,  0, sizeof(float)*BATCH*2*HD);
    cudaMemsetAsync(p_gi,   0, sizeof(float)*BATCH*G3H);
    cudaMemsetAsync(p_gh,   0, sizeof(float)*BATCH*G3H);

    k_weff   <<<dim3(8,8),   128>>>(attn_w, v);
    k_scores <<<3200,        256>>>(enc);
    k_softmax<<<BATCH,       256>>>();
    k_ctx    <<<dim3(BATCH,4),256>>>(enc);
    k_pack   <<<BATCH,       256>>>(emb, x);

    // GRU gate GEMMs (split-K)
    sgemm_sk<<<dim3(G3H/64, 5), 256>>>(p_togru, w_ih, p_gi, G3H, KGRU, G3H, 256);
    sgemm_sk<<<dim3(G3H/64, 2), 256>>>(hidden,  w_hh, p_gh, G3H, HD,   G3H, 256);

    int write_h = (out_size >= BATCH*VOCAB + BATCH*HD) ? 1 : 0;
    k_gru<<<(BATCH*HD)/256, 256>>>(hidden, b_ih, b_hh, out + (size_t)BATCH*VOCAB, write_h);

    // logits via TF32 tensor cores
    k_logits<<<(VOCAB + 127)/128, 256>>>(p_toout, out_w, out_b, out);
}

// round 4
// speedup vs baseline: 2.5303x; 1.0644x over previous
#include <cuda_runtime.h>
#include <math.h>
#include <stdint.h>

#define HD    512
#define EMBD  256
#define VOCAB 50000
#define BATCH 128
#define SEQ   200
#define G3H   (3*HD)       // 1536
#define KGRU  (2*HD+EMBD)  // 1280
#define KOUT  (3*HD+EMBD)  // 1792

// Scratch (device globals — no allocation allowed)
__device__ float g_weff[2*HD];
__device__ float g_togru[BATCH*KGRU];
__device__ float g_toout[BATCH*KOUT];
__device__ float g_gi[BATCH*G3H];
__device__ float g_gh[BATCH*G3H];

// ---------------------------------------------------------------------------
// helpers
// ---------------------------------------------------------------------------
__device__ __forceinline__ uint32_t f2tf32(float x) {
    uint32_t r;
    asm("cvt.rna.tf32.f32 %0, %1;" : "=r"(r) : "f"(x));
    return r;
}

__device__ __forceinline__ void mma_tf32(float* c, const uint32_t* a, const uint32_t* b) {
    asm volatile(
        "mma.sync.aligned.m16n8k8.row.col.f32.tf32.tf32.f32 "
        "{%0,%1,%2,%3}, {%4,%5,%6,%7}, {%8,%9}, {%0,%1,%2,%3};"
        : "+f"(c[0]), "+f"(c[1]), "+f"(c[2]), "+f"(c[3])
        : "r"(a[0]), "r"(a[1]), "r"(a[2]), "r"(a[3]), "r"(b[0]), "r"(b[1]));
}

__device__ __forceinline__ void cp_async16(void* dst_smem, const void* src, int src_bytes) {
    uint32_t dst = (uint32_t)__cvta_generic_to_shared(dst_smem);
    asm volatile("cp.async.cg.shared.global [%0], [%1], 16, %2;\n"
                 :: "r"(dst), "l"(src), "r"(src_bytes));
}

// ---------------------------------------------------------------------------
// K0: w_eff[k] = sum_h v[h]*attn_w[h,512+k]  (h0 part + attn_b cancel in softmax)
// ---------------------------------------------------------------------------
__global__ void k_weff(const float* __restrict__ attn_w, const float* __restrict__ v) {
    int k  = blockIdx.x * 128 + threadIdx.x;
    int h0 = blockIdx.y * 64;
    float s = 0.f;
    #pragma unroll 8
    for (int h = h0; h < h0 + 64; ++h)
        s += v[h] * attn_w[(size_t)h * G3H + HD + k];
    atomicAdd(&g_weff[k], s);
}

// ---------------------------------------------------------------------------
// K1: fused attention: scores + softmax + context + pack (one block per batch)
// Phase 1 streams enc (fills L2), phase 3 re-reads it from L2.
// ---------------------------------------------------------------------------
__global__ __launch_bounds__(512) void k_attn(const float* __restrict__ enc,
                                              const float* __restrict__ emb,
                                              const int* __restrict__ x) {
    __shared__ float sw[2*HD];
    __shared__ float attn[256];
    __shared__ float red[512];
    int b = blockIdx.x, tid = threadIdx.x;
    for (int i = tid; i < 2*HD; i += 512) sw[i] = g_weff[i];
    __syncthreads();

    int warp = tid >> 5, lane = tid & 31;
    const float* pb = enc + (size_t)b * SEQ * (2*HD);

    // phase 1: scores (one warp per s, strided)
    for (int s = warp; s < SEQ; s += 16) {
        const float* p = pb + s * (2*HD);
        float acc = 0.f;
        #pragma unroll
        for (int i = 0; i < 32; ++i)
            acc += p[lane + 32*i] * sw[lane + 32*i];
        #pragma unroll
        for (int o = 16; o; o >>= 1) acc += __shfl_xor_sync(0xffffffffu, acc, o);
        if (lane == 0) attn[s] = acc;
    }
    __syncthreads();

    // phase 2: softmax over S=200
    float sc = (tid < SEQ) ? attn[tid] : -1e30f;
    red[tid] = sc; __syncthreads();
    #pragma unroll
    for (int o = 256; o; o >>= 1) { if (tid < o) red[tid] = fmaxf(red[tid], red[tid+o]); __syncthreads(); }
    float mx = red[0]; __syncthreads();
    float e = (tid < SEQ) ? expf(sc - mx) : 0.f;
    red[tid] = e; __syncthreads();
    #pragma unroll
    for (int o = 256; o; o >>= 1) { if (tid < o) red[tid] += red[tid+o]; __syncthreads(); }
    float inv = 1.f / red[0];
    __syncthreads();
    if (tid < SEQ) attn[tid] = e * inv;
    __syncthreads();

    // phase 3: context (each thread: dims tid and tid+512) — enc from L2
    float a0 = 0.f, a1 = 0.f;
    #pragma unroll 4
    for (int s = 0; s < SEQ; ++s) {
        float a = attn[s];
        const float* p = pb + s * (2*HD);
        a0 += a * p[tid];
        a1 += a * p[tid + 512];
    }

    // phase 4: pack outputs
    g_toout[(size_t)b*KOUT + HD + tid]       = a0;
    g_toout[(size_t)b*KOUT + HD + tid + 512] = a1;
    g_togru[(size_t)b*KGRU + EMBD + tid]       = fmaxf(a0, 0.f);
    g_togru[(size_t)b*KGRU + EMBD + tid + 512] = fmaxf(a1, 0.f);
    if (tid < EMBD) {
        float ev = emb[(size_t)x[b] * EMBD + tid];
        g_togru[(size_t)b*KGRU + tid]        = fmaxf(ev, 0.f);
        g_toout[(size_t)b*KOUT + 3*HD + tid] = ev;
    }
}

// ---------------------------------------------------------------------------
// Split-K SGEMM (fp32): C[m,n] += sum_{k in slice} A[m,k]*B[n,k] via atomicAdd
// ---------------------------------------------------------------------------
__global__ __launch_bounds__(256, 2) void sgemm_sk(
    const float* __restrict__ A, const float* __restrict__ Bm,
    float* __restrict__ C, int N, int K, int ldc, int kslice)
{
    __shared__ float As[16][128];
    __shared__ float Bs[16][64];
    int tid = threadIdx.x;
    int n0  = blockIdx.x * 64;
    int kb  = blockIdx.y * kslice;
    int ke  = kb + kslice; if (ke > K) ke = K;
    int tx  = tid & 15;
    int ty  = tid >> 4;

    float acc[8][4];
    #pragma unroll
    for (int i = 0; i < 8; ++i)
        #pragma unroll
        for (int j = 0; j < 4; ++j) acc[i][j] = 0.f;

    for (int k0 = kb; k0 < ke; k0 += 16) {
        #pragma unroll
        for (int r = 0; r < 2; ++r) {
            int l = tid + 256*r;
            int m = l >> 2, kq = l & 3;
            float4 f = *(const float4*)(A + (size_t)m * K + k0 + kq*4);
            As[kq*4+0][m] = f.x; As[kq*4+1][m] = f.y;
            As[kq*4+2][m] = f.z; As[kq*4+3][m] = f.w;
        }
        {
            int n = tid >> 2, kq = tid & 3;
            float4 f = make_float4(0.f, 0.f, 0.f, 0.f);
            if (n0 + n < N)
                f = *(const float4*)(Bm + (size_t)(n0+n) * K + k0 + kq*4);
            Bs[kq*4+0][n] = f.x; Bs[kq*4+1][n] = f.y;
            Bs[kq*4+2][n] = f.z; Bs[kq*4+3][n] = f.w;
        }
        __syncthreads();
        #pragma unroll
        for (int kk = 0; kk < 16; ++kk) {
            float4 b4  = *(const float4*)&Bs[kk][tx*4];
            float4 a4a = *(const float4*)&As[kk][ty*8];
            float4 a4b = *(const float4*)&As[kk][ty*8+4];
            float af[8] = {a4a.x,a4a.y,a4a.z,a4a.w, a4b.x,a4b.y,a4b.z,a4b.w};
            float bf[4] = {b4.x,b4.y,b4.z,b4.w};
            #pragma unroll
            for (int i = 0; i < 8; ++i)
                #pragma unroll
                for (int j = 0; j < 4; ++j)
                    acc[i][j] = fmaf(af[i], bf[j], acc[i][j]);
        }
        __syncthreads();
    }

    int n = n0 + tx*4;
    if (n < N) {
        #pragma unroll
        for (int i = 0; i < 8; ++i) {
            int m = ty*8 + i;
            #pragma unroll
            for (int j = 0; j < 4; ++j)
                atomicAdd(&C[(size_t)m * ldc + n + j], acc[i][j]);
        }
    }
}

// ---------------------------------------------------------------------------
// K5: GRU gate combine (biases here) -> h_new into to_out + d_out tail
// ---------------------------------------------------------------------------
__global__ void k_gru(const float* __restrict__ hidden,
                      const float* __restrict__ b_ih, const float* __restrict__ b_hh,
                      float* __restrict__ out_h, int write_h) {
    int idx = blockIdx.x * blockDim.x + threadIdx.x;
    int b = idx >> 9, i = idx & 511;
    size_t base = (size_t)b * G3H;
    float ir = g_gi[base + i]        + b_ih[i];
    float hr = g_gh[base + i]        + b_hh[i];
    float iz = g_gi[base + HD + i]   + b_ih[HD + i];
    float hz = g_gh[base + HD + i]   + b_hh[HD + i];
    float in_= g_gi[base + 2*HD + i] + b_ih[2*HD + i];
    float hn = g_gh[base + 2*HD + i] + b_hh[2*HD + i];
    float r = 1.f / (1.f + expf(-(ir + hr)));
    float z = 1.f / (1.f + expf(-(iz + hz)));
    float n = tanhf(in_ + r * hn);
    float h = hidden[idx];
    float hnew = (1.f - z) * n + z * h;
    g_toout[(size_t)b * KOUT + i] = hnew;
    if (write_h) out_h[idx] = hnew;
}

// ---------------------------------------------------------------------------
// K6: logits GEMM, TF32 mma, 4-stage cp.async pipeline
// BM=128, BN=128, BK=16; 8 warps (4M x 2N); raw fp32 in smem, cvt at frag load
// ---------------------------------------------------------------------------
#define STAGES 4
#define BK 16
#define LDA 20                         // padded k-stride (floats)
#define STAGE_F (128*LDA)              // floats per stage per matrix

extern __shared__ float s_pipe[];      // [STAGES*STAGE_F A][STAGES*STAGE_F B]

__global__ __launch_bounds__(256, 2) void k_logits(
    const float* __restrict__ A, const float* __restrict__ Bw,
    const float* __restrict__ bias, float* __restrict__ C)
{
    float* Asm = s_pipe;
    float* Bsm = s_pipe + STAGES*STAGE_F;
    int tid  = threadIdx.x;
    int wid  = tid >> 5, lane = tid & 31;
    int gid  = lane >> 2, tig = lane & 3;
    int n0   = blockIdx.x * 128;
    int wm   = (wid & 3) * 32;
    int wn   = (wid >> 2) * 64;
    int lm   = tid >> 2;               // 0..63
    int lk   = (tid & 3) * 4;          // 0,4,8,12

    const int KT = KOUT / BK;          // 112

    auto issue = [&](int kt) {
        int st = kt & (STAGES-1);
        int k0 = kt * BK;
        float* as = Asm + st*STAGE_F;
        float* bs = Bsm + st*STAGE_F;
        #pragma unroll
        for (int h = 0; h < 2; ++h) {
            int m = lm + h*64;
            cp_async16(as + m*LDA + lk, A + (size_t)m*KOUT + k0 + lk, 16);
        }
        #pragma unroll
        for (int h = 0; h < 2; ++h) {
            int n = lm + h*64;
            int gn = n0 + n;
            cp_async16(bs + n*LDA + lk, Bw + (size_t)gn*KOUT + k0 + lk,
                       (gn < VOCAB) ? 16 : 0);
        }
    };

    float acc[2][8][4];
    #pragma unroll
    for (int mt = 0; mt < 2; ++mt)
        #pragma unroll
        for (int nt = 0; nt < 8; ++nt)
            #pragma unroll
            for (int j = 0; j < 4; ++j) acc[mt][nt][j] = 0.f;

    #pragma unroll
    for (int s = 0; s < STAGES-1; ++s) {
        issue(s);
        asm volatile("cp.async.commit_group;\n" ::: "memory");
    }

    for (int kt = 0; kt < KT; ++kt) {
        asm volatile("cp.async.wait_group %0;\n" :: "n"(STAGES-2) : "memory");
        __syncthreads();

        // prefetch STAGES-1 ahead (overwrites stage computed at kt-1; safe past the sync)
        int nk = kt + STAGES - 1;
        if (nk < KT) issue(nk);
        asm volatile("cp.async.commit_group;\n" ::: "memory");

        int st = kt & (STAGES-1);
        const float* as = Asm + st*STAGE_F;
        const float* bs = Bsm + st*STAGE_F;
        #pragma unroll
        for (int ks = 0; ks < 2; ++ks) {
            int kb = ks * 8;
            uint32_t af[2][4];
            #pragma unroll
            for (int mt = 0; mt < 2; ++mt) {
                int r = wm + mt*16;
                af[mt][0] = f2tf32(as[(r + gid    )*LDA + kb + tig    ]);
                af[mt][1] = f2tf32(as[(r + gid + 8)*LDA + kb + tig    ]);
                af[mt][2] = f2tf32(as[(r + gid    )*LDA + kb + tig + 4]);
                af[mt][3] = f2tf32(as[(r + gid + 8)*LDA + kb + tig + 4]);
            }
            #pragma unroll
            for (int nt = 0; nt < 8; ++nt) {
                uint32_t bf[2];
                int nn = wn + nt*8 + gid;
                bf[0] = f2tf32(bs[nn*LDA + kb + tig    ]);
                bf[1] = f2tf32(bs[nn*LDA + kb + tig + 4]);
                mma_tf32(acc[0][nt], af[0], bf);
                mma_tf32(acc[1][nt], af[1], bf);
            }
        }
    }

    #pragma unroll
    for (int mt = 0; mt < 2; ++mt) {
        #pragma unroll
        for (int nt = 0; nt < 8; ++nt) {
            int n = n0 + wn + nt*8 + 2*tig;
            if (n < VOCAB) {
                int m = wm + mt*16 + gid;
                float b0 = bias[n], b1 = bias[n+1];
                float2 v0 = make_float2(acc[mt][nt][0] + b0, acc[mt][nt][1] + b1);
                float2 v1 = make_float2(acc[mt][nt][2] + b0, acc[mt][nt][3] + b1);
                *(float2*)(C + (size_t)m     * VOCAB + n) = v0;
                *(float2*)(C + (size_t)(m+8) * VOCAB + n) = v1;
            }
        }
    }
}

// ---------------------------------------------------------------------------
extern "C" void kernel_launch(void* const* d_in, const int* in_sizes, int n_in,
                              void* d_out, int out_size) {
    const int*   x      = (const int*)  d_in[0];
    const float* hidden = (const float*)d_in[1];
    const float* enc    = (const float*)d_in[2];
    const float* emb    = (const float*)d_in[3];
    const float* attn_w = (const float*)d_in[4];
    // d_in[5] = attn_b : cancels under softmax
    const float* v      = (const float*)d_in[6];
    const float* w_ih   = (const float*)d_in[7];
    const float* w_hh   = (const float*)d_in[8];
    const float* b_ih   = (const float*)d_in[9];
    const float* b_hh   = (const float*)d_in[10];
    const float* out_w  = (const float*)d_in[11];
    const float* out_b  = (const float*)d_in[12];
    float* out = (float*)d_out;

    float *p_weff, *p_togru, *p_toout, *p_gi, *p_gh;
    cudaGetSymbolAddress((void**)&p_weff,  g_weff);
    cudaGetSymbolAddress((void**)&p_togru, g_togru);
    cudaGetSymbolAddress((void**)&p_toout, g_toout);
    cudaGetSymbolAddress((void**)&p_gi,    g_gi);
    cudaGetSymbolAddress((void**)&p_gh,    g_gh);

    cudaMemsetAsync(p_weff, 0, sizeof(float)*2*HD);
    cudaMemsetAsync(p_gi,   0, sizeof(float)*BATCH*G3H);
    cudaMemsetAsync(p_gh,   0, sizeof(float)*BATCH*G3H);

    k_weff<<<dim3(8,8), 128>>>(attn_w, v);
    k_attn<<<BATCH, 512>>>(enc, emb, x);

    // GRU gate GEMMs (split-K)
    sgemm_sk<<<dim3(G3H/64, 5), 256>>>(p_togru, w_ih, p_gi, G3H, KGRU, G3H, 256);
    sgemm_sk<<<dim3(G3H/64, 2), 256>>>(hidden,  w_hh, p_gh, G3H, HD,   G3H, 256);

    int write_h = (out_size >= BATCH*VOCAB + BATCH*HD) ? 1 : 0;
    k_gru<<<(BATCH*HD)/256, 256>>>(hidden, b_ih, b_hh, out + (size_t)BATCH*VOCAB, write_h);

    // logits via pipelined TF32 tensor cores
    size_t smem = (size_t)2 * STAGES * STAGE_F * sizeof(float);   // 81920
    cudaFuncSetAttribute(k_logits, cudaFuncAttributeMaxDynamicSharedMemorySize, (int)smem);
    k_logits<<<(VOCAB + 127)/128, 256, smem>>>(p_toout, out_w, out_b, out);
}

// round 6
// speedup vs baseline: 2.9806x; 1.1780x over previous
#include <cuda_runtime.h>
#include <math.h>
#include <stdint.h>

#define HD    512
#define EMBD  256
#define VOCAB 50000
#define BATCH 128
#define SEQ   200
#define G3H   (3*HD)       // 1536
#define KGRU  (2*HD+EMBD)  // 1280
#define KOUT  (3*HD+EMBD)  // 1792

#define SLICE_IH 10        // split-K slices for w_ih GEMM
#define SLICE_HH 4         // split-K slices for w_hh GEMM

// Scratch (device globals — no allocation allowed)
__device__ float g_weff_part[8][1024];
__device__ float g_togru[BATCH*KGRU];
__device__ float g_toout[BATCH*KOUT];
__device__ float g_gi[SLICE_IH][BATCH*G3H];
__device__ float g_gh[SLICE_HH][BATCH*G3H];

// ---------------------------------------------------------------------------
// helpers
// ---------------------------------------------------------------------------
__device__ __forceinline__ uint32_t f2tf32(float x) {
    uint32_t r;
    asm("cvt.rna.tf32.f32 %0, %1;" : "=r"(r) : "f"(x));
    return r;
}
__device__ __forceinline__ float tf32r(float x) { return __uint_as_float(f2tf32(x)); }

__device__ __forceinline__ void mma_tf32(float* c, const uint32_t* a, const uint32_t* b) {
    asm volatile(
        "mma.sync.aligned.m16n8k8.row.col.f32.tf32.tf32.f32 "
        "{%0,%1,%2,%3}, {%4,%5,%6,%7}, {%8,%9}, {%0,%1,%2,%3};"
        : "+f"(c[0]), "+f"(c[1]), "+f"(c[2]), "+f"(c[3])
        : "r"(a[0]), "r"(a[1]), "r"(a[2]), "r"(a[3]), "r"(b[0]), "r"(b[1]));
}

__device__ __forceinline__ void cp_async16(uint32_t dst_smem, const void* src, int src_bytes) {
    asm volatile("cp.async.cg.shared.global [%0], [%1], 16, %2;\n"
                 :: "r"(dst_smem), "l"(src), "r"(src_bytes));
}

// ---------------------------------------------------------------------------
// K0: w_eff partials: part[y][k] = sum_{h in chunk y} v[h]*attn_w[h,512+k]
// (h0 part + attn_b cancel under softmax)
// ---------------------------------------------------------------------------
__global__ void k_weff(const float* __restrict__ attn_w, const float* __restrict__ v) {
    int k  = blockIdx.x * 256 + threadIdx.x;
    int h0 = blockIdx.y * 64;
    float s = 0.f;
    #pragma unroll 16
    for (int h = h0; h < h0 + 64; ++h)
        s += v[h] * attn_w[(size_t)h * G3H + HD + k];
    g_weff_part[blockIdx.y][k] = s;
}

// ---------------------------------------------------------------------------
// K1: fused attention: scores + softmax + context + pack (one block per batch)
// ---------------------------------------------------------------------------
__global__ __launch_bounds__(512) void k_attn(const float* __restrict__ enc,
                                              const float* __restrict__ emb,
                                              const int* __restrict__ x) {
    __shared__ float sw[2*HD];
    __shared__ float attn[256];
    __shared__ float red[512];
    int b = blockIdx.x, tid = threadIdx.x;
    for (int i = tid; i < 2*HD; i += 512) {
        float s = 0.f;
        #pragma unroll
        for (int y = 0; y < 8; ++y) s += g_weff_part[y][i];
        sw[i] = s;
    }
    __syncthreads();

    int warp = tid >> 5, lane = tid & 31;
    const float* pb = enc + (size_t)b * SEQ * (2*HD);

    for (int s = warp; s < SEQ; s += 16) {
        const float* p = pb + s * (2*HD);
        float acc = 0.f;
        #pragma unroll
        for (int i = 0; i < 32; ++i)
            acc += p[lane + 32*i] * sw[lane + 32*i];
        #pragma unroll
        for (int o = 16; o; o >>= 1) acc += __shfl_xor_sync(0xffffffffu, acc, o);
        if (lane == 0) attn[s] = acc;
    }
    __syncthreads();

    float sc = (tid < SEQ) ? attn[tid] : -1e30f;
    red[tid] = sc; __syncthreads();
    #pragma unroll
    for (int o = 256; o; o >>= 1) { if (tid < o) red[tid] = fmaxf(red[tid], red[tid+o]); __syncthreads(); }
    float mx = red[0]; __syncthreads();
    float e = (tid < SEQ) ? expf(sc - mx) : 0.f;
    red[tid] = e; __syncthreads();
    #pragma unroll
    for (int o = 256; o; o >>= 1) { if (tid < o) red[tid] += red[tid+o]; __syncthreads(); }
    float inv = 1.f / red[0];
    __syncthreads();
    if (tid < SEQ) attn[tid] = e * inv;
    __syncthreads();

    float a0 = 0.f, a1 = 0.f;
    #pragma unroll 4
    for (int s = 0; s < SEQ; ++s) {
        float a = attn[s];
        const float* p = pb + s * (2*HD);
        a0 += a * p[tid];
        a1 += a * p[tid + 512];
    }

    g_toout[(size_t)b*KOUT + HD + tid]       = tf32r(a0);   // pre-rounded for tf32 mma
    g_toout[(size_t)b*KOUT + HD + tid + 512] = tf32r(a1);
    g_togru[(size_t)b*KGRU + EMBD + tid]       = fmaxf(a0, 0.f);
    g_togru[(size_t)b*KGRU + EMBD + tid + 512] = fmaxf(a1, 0.f);
    if (tid < EMBD) {
        float ev = emb[(size_t)x[b] * EMBD + tid];
        g_togru[(size_t)b*KGRU + tid]        = fmaxf(ev, 0.f);
        g_toout[(size_t)b*KOUT + 3*HD + tid] = tf32r(ev);
    }
}

// ---------------------------------------------------------------------------
// Split-K SGEMM (fp32): per-slice output buffers (no atomics, no zeroing)
// C_slice[blockIdx.y][m,n] = sum_{k in slice} A[m,k]*B[n,k]
// ---------------------------------------------------------------------------
__global__ __launch_bounds__(256, 2) void sgemm_sk(
    const float* __restrict__ A, const float* __restrict__ Bm,
    float* __restrict__ C, int N, int K, int ldc, int kslice, int cstride)
{
    __shared__ float As[16][128];
    __shared__ float Bs[16][64];
    int tid = threadIdx.x;
    int n0  = blockIdx.x * 64;
    int kb  = blockIdx.y * kslice;
    int ke  = kb + kslice; if (ke > K) ke = K;
    int tx  = tid & 15;
    int ty  = tid >> 4;
    float* Cs = C + (size_t)blockIdx.y * cstride;

    float acc[8][4];
    #pragma unroll
    for (int i = 0; i < 8; ++i)
        #pragma unroll
        for (int j = 0; j < 4; ++j) acc[i][j] = 0.f;

    for (int k0 = kb; k0 < ke; k0 += 16) {
        #pragma unroll
        for (int r = 0; r < 2; ++r) {
            int l = tid + 256*r;
            int m = l >> 2, kq = l & 3;
            float4 f = *(const float4*)(A + (size_t)m * K + k0 + kq*4);
            As[kq*4+0][m] = f.x; As[kq*4+1][m] = f.y;
            As[kq*4+2][m] = f.z; As[kq*4+3][m] = f.w;
        }
        {
            int n = tid >> 2, kq = tid & 3;
            float4 f = make_float4(0.f, 0.f, 0.f, 0.f);
            if (n0 + n < N)
                f = *(const float4*)(Bm + (size_t)(n0+n) * K + k0 + kq*4);
            Bs[kq*4+0][n] = f.x; Bs[kq*4+1][n] = f.y;
            Bs[kq*4+2][n] = f.z; Bs[kq*4+3][n] = f.w;
        }
        __syncthreads();
        #pragma unroll
        for (int kk = 0; kk < 16; ++kk) {
            float4 b4  = *(const float4*)&Bs[kk][tx*4];
            float4 a4a = *(const float4*)&As[kk][ty*8];
            float4 a4b = *(const float4*)&As[kk][ty*8+4];
            float af[8] = {a4a.x,a4a.y,a4a.z,a4a.w, a4b.x,a4b.y,a4b.z,a4b.w};
            float bf[4] = {b4.x,b4.y,b4.z,b4.w};
            #pragma unroll
            for (int i = 0; i < 8; ++i)
                #pragma unroll
                for (int j = 0; j < 4; ++j)
                    acc[i][j] = fmaf(af[i], bf[j], acc[i][j]);
        }
        __syncthreads();
    }

    int n = n0 + tx*4;
    if (n < N) {
        #pragma unroll
        for (int i = 0; i < 8; ++i) {
            int m = ty*8 + i;
            float4 o = make_float4(acc[i][0], acc[i][1], acc[i][2], acc[i][3]);
            *(float4*)(Cs + (size_t)m * ldc + n) = o;
        }
    }
}

// ---------------------------------------------------------------------------
// K5: GRU gate combine (sums split-K slices, adds biases) -> h_new
// ---------------------------------------------------------------------------
__global__ void k_gru(const float* __restrict__ hidden,
                      const float* __restrict__ b_ih, const float* __restrict__ b_hh,
                      float* __restrict__ out_h, int write_h) {
    int idx = blockIdx.x * blockDim.x + threadIdx.x;
    int b = idx >> 9, i = idx & 511;
    size_t base = (size_t)b * G3H;

    float ir = b_ih[i], iz = b_ih[HD + i], in_ = b_ih[2*HD + i];
    #pragma unroll
    for (int s = 0; s < SLICE_IH; ++s) {
        ir  += g_gi[s][base + i];
        iz  += g_gi[s][base + HD + i];
        in_ += g_gi[s][base + 2*HD + i];
    }
    float hr = b_hh[i], hz = b_hh[HD + i], hn = b_hh[2*HD + i];
    #pragma unroll
    for (int s = 0; s < SLICE_HH; ++s) {
        hr += g_gh[s][base + i];
        hz += g_gh[s][base + HD + i];
        hn += g_gh[s][base + 2*HD + i];
    }
    float r = 1.f / (1.f + expf(-(ir + hr)));
    float z = 1.f / (1.f + expf(-(iz + hz)));
    float n = tanhf(in_ + r * hn);
    float h = hidden[idx];
    float hnew = (1.f - z) * n + z * h;
    g_toout[(size_t)b * KOUT + i] = tf32r(hnew);   // pre-rounded for tf32 mma
    if (write_h) out_h[idx] = hnew;
}

// ---------------------------------------------------------------------------
// K6: logits GEMM, TF32 mma.sync, 3-stage cp.async, BK=32.
// BM=128, BN=128; 8 warps (4M x 2N), warp tile 32x64.
// A fragments: raw bits (A pre-rounded to tf32) — no cvt. B: cvt at frag load.
// ---------------------------------------------------------------------------
#define STG   3
#define BKL   32
#define LDAL  36                        // floats per smem row (32 + 4 pad)
#define STG_F (128*LDAL)                // floats per matrix per stage
#define KTL   (KOUT/BKL)                // 56

extern __shared__ float s_pipe[];

__global__ __launch_bounds__(256, 2) void k_logits(
    const float* __restrict__ A, const float* __restrict__ Bw,
    const float* __restrict__ bias, float* __restrict__ C)
{
    uint32_t su = (uint32_t)__cvta_generic_to_shared(s_pipe);
    int tid  = threadIdx.x;
    int wid  = tid >> 5, lane = tid & 31;
    int gid  = lane >> 2, tig = lane & 3;
    int n0   = blockIdx.x * 128;
    int wm   = (wid & 3) * 32;
    int wn   = (wid >> 2) * 64;

    int lr = tid >> 3;                  // 0..31 base row (each thread: 4 rows via +32)
    int lc = (tid & 7) * 16;            // byte offset within 128B row

    auto issue = [&](int kt) {
        int st = kt % STG;
        uint32_t abase = su + st * (2*STG_F*4);
        uint32_t bbase = abase + STG_F*4;
        const float* Asrc = A  + (size_t)kt*BKL;
        const float* Bsrc = Bw + (size_t)n0*KOUT + (size_t)kt*BKL;
        #pragma unroll
        for (int j = 0; j < 4; ++j) {
            int r = lr + j*32;
            uint32_t doff = (uint32_t)r*(LDAL*4) + lc;
            cp_async16(abase + doff, (const char*)(Asrc + (size_t)r*KOUT) + lc, 16);
            cp_async16(bbase + doff, (const char*)(Bsrc + (size_t)r*KOUT) + lc,
                       (n0 + r < VOCAB) ? 16 : 0);
        }
        asm volatile("cp.async.commit_group;\n" ::: "memory");
    };

    float acc[2][8][4];
    #pragma unroll
    for (int mt = 0; mt < 2; ++mt)
        #pragma unroll
        for (int nt = 0; nt < 8; ++nt)
            #pragma unroll
            for (int j = 0; j < 4; ++j) acc[mt][nt][j] = 0.f;

    issue(0);
    issue(1);

    for (int kt = 0; kt < KTL; ++kt) {
        asm volatile("cp.async.wait_group %0;\n" :: "n"(STG-2) : "memory");
        __syncthreads();

        int nk = kt + STG - 1;
        if (nk < KTL) issue(nk);        // overwrites stage computed at kt-1

        int st = kt % STG;
        const float* as = s_pipe + st * (2*STG_F);
        const float* bs = as + STG_F;

        #pragma unroll
        for (int ks = 0; ks < 4; ++ks) {
            int kb = ks * 8;
            uint32_t af[2][4];
            #pragma unroll
            for (int mt = 0; mt < 2; ++mt) {
                int r = wm + mt*16;
                af[mt][0] = __float_as_uint(as[(r + gid    )*LDAL + kb + tig    ]);
                af[mt][1] = __float_as_uint(as[(r + gid + 8)*LDAL + kb + tig    ]);
                af[mt][2] = __float_as_uint(as[(r + gid    )*LDAL + kb + tig + 4]);
                af[mt][3] = __float_as_uint(as[(r + gid + 8)*LDAL + kb + tig + 4]);
            }
            #pragma unroll
            for (int nt = 0; nt < 8; ++nt) {
                uint32_t bf[2];
                int nn = wn + nt*8 + gid;
                bf[0] = f2tf32(bs[nn*LDAL + kb + tig    ]);
                bf[1] = f2tf32(bs[nn*LDAL + kb + tig + 4]);
                mma_tf32(acc[0][nt], af[0], bf);
                mma_tf32(acc[1][nt], af[1], bf);
            }
        }
    }

    #pragma unroll
    for (int mt = 0; mt < 2; ++mt) {
        #pragma unroll
        for (int nt = 0; nt < 8; ++nt) {
            int n = n0 + wn + nt*8 + 2*tig;
            if (n < VOCAB) {
                int m = wm + mt*16 + gid;
                float b0 = bias[n], b1 = bias[n+1];
                float2 v0 = make_float2(acc[mt][nt][0] + b0, acc[mt][nt][1] + b1);
                float2 v1 = make_float2(acc[mt][nt][2] + b0, acc[mt][nt][3] + b1);
                *(float2*)(C + (size_t)m     * VOCAB + n) = v0;
                *(float2*)(C + (size_t)(m+8) * VOCAB + n) = v1;
            }
        }
    }
}

// ---------------------------------------------------------------------------
extern "C" void kernel_launch(void* const* d_in, const int* in_sizes, int n_in,
                              void* d_out, int out_size) {
    const int*   x      = (const int*)  d_in[0];
    const float* hidden = (const float*)d_in[1];
    const float* enc    = (const float*)d_in[2];
    const float* emb    = (const float*)d_in[3];
    const float* attn_w = (const float*)d_in[4];
    // d_in[5] = attn_b : cancels under softmax
    const float* v      = (const float*)d_in[6];
    const float* w_ih   = (const float*)d_in[7];
    const float* w_hh   = (const float*)d_in[8];
    const float* b_ih   = (const float*)d_in[9];
    const float* b_hh   = (const float*)d_in[10];
    const float* out_w  = (const float*)d_in[11];
    const float* out_b  = (const float*)d_in[12];
    float* out = (float*)d_out;

    float *p_togru, *p_toout, *p_gi, *p_gh;
    cudaGetSymbolAddress((void**)&p_togru, g_togru);
    cudaGetSymbolAddress((void**)&p_toout, g_toout);
    cudaGetSymbolAddress((void**)&p_gi,    g_gi);
    cudaGetSymbolAddress((void**)&p_gh,    g_gh);

    // launches 1..6 (ncu -s 5 -c 1 profiles #6 = k_logits)
    k_weff<<<dim3(4,8), 256>>>(attn_w, v);                                     // 1
    k_attn<<<BATCH, 512>>>(enc, emb, x);                                       // 2
    sgemm_sk<<<dim3(G3H/64, SLICE_IH), 256>>>(p_togru, w_ih, p_gi,             // 3
                                              G3H, KGRU, G3H, KGRU/SLICE_IH, BATCH*G3H);
    sgemm_sk<<<dim3(G3H/64, SLICE_HH), 256>>>(hidden,  w_hh, p_gh,             // 4
                                              G3H, HD,   G3H, HD/SLICE_HH,  BATCH*G3H);
    int write_h = (out_size >= BATCH*VOCAB + BATCH*HD) ? 1 : 0;
    k_gru<<<(BATCH*HD)/256, 256>>>(hidden, b_ih, b_hh,                         // 5
                                   out + (size_t)BATCH*VOCAB, write_h);

    size_t smem = (size_t)STG * 2 * STG_F * sizeof(float);                     // 110592
    cudaFuncSetAttribute(k_logits, cudaFuncAttributeMaxDynamicSharedMemorySize, (int)smem);
    k_logits<<<(VOCAB + 127)/128, 256, smem>>>(p_toout, out_w, out_b, out);    // 6
}